// round 1
// baseline (speedup 1.0000x reference)
#include <cuda_runtime.h>
#include <math.h>

#define N_PIX 4096
#define CDIM  256
#define HID   128
#define NH    4
#define DH    32
#define BATCH 2
#define ATT_SCALE 0.17677669529663687f   // 32^-0.5

// ---------------- scratch (static device globals; no allocs) ----------------
__device__ float g_q [BATCH * NH * N_PIX * DH];   // [b][h][n][f]
__device__ float g_k [BATCH * NH * N_PIX * DH];
__device__ float g_v [BATCH * NH * N_PIX * DH];
__device__ float g_ao[BATCH * HID * N_PIX];       // [b][h*32+f][n]
__device__ float g_scl[BATCH * N_PIX];            // per-pixel 16/max(||x||,eps)

// ---------------- kernel 1: per-pixel channel-norm scale ----------------
__global__ void norm_kernel(const float* __restrict__ x) {
    int p   = blockIdx.x * 256 + threadIdx.x;     // 0..8191
    int b   = p >> 12;
    int pix = p & (N_PIX - 1);
    const float* xb = x + (size_t)b * CDIM * N_PIX + pix;
    float ss = 0.f;
#pragma unroll 8
    for (int c = 0; c < CDIM; c++) {
        float v = xb[(size_t)c * N_PIX];
        ss += v * v;
    }
    float nrm = sqrtf(ss);
    g_scl[p] = 16.0f / fmaxf(nrm, 1e-12f);        // sqrt(256)/clamp(norm)
}

// ---------------- kernel 2: QKV GEMM (384x256 @ 256x4096 per batch) ----------------
// C[o][p] = scale_p * sum_c (w_qkv[o][c]*g[c]) * x[b][c][p], routed into q/k/v.
__global__ void qkv_gemm(const float* __restrict__ x,
                         const float* __restrict__ gvec,
                         const float* __restrict__ w) {
    __shared__ float As[16][64];   // [k][m]
    __shared__ float Bs[16][64];   // [k][n]
    int b    = blockIdx.z;
    int row0 = blockIdx.y * 64;    // o
    int col0 = blockIdx.x * 64;    // p
    int tid  = threadIdx.x;        // 256
    int tx = tid & 15, ty = tid >> 4;

    const float* Bbase = x + (size_t)b * CDIM * N_PIX;
    float acc[4][4];
#pragma unroll
    for (int i = 0; i < 4; i++)
#pragma unroll
        for (int j = 0; j < 4; j++) acc[i][j] = 0.f;

    int am = tid >> 2;            // 0..63
    int ak = (tid & 3) * 4;       // 0,4,8,12
    int bk = tid >> 4;            // 0..15
    int bn = (tid & 15) * 4;

    for (int k0 = 0; k0 < CDIM; k0 += 16) {
        float4 av = *(const float4*)&w[(size_t)(row0 + am) * CDIM + k0 + ak];
        float4 gv = *(const float4*)&gvec[k0 + ak];
        As[ak + 0][am] = av.x * gv.x;
        As[ak + 1][am] = av.y * gv.y;
        As[ak + 2][am] = av.z * gv.z;
        As[ak + 3][am] = av.w * gv.w;
        *(float4*)&Bs[bk][bn] =
            *(const float4*)&Bbase[(size_t)(k0 + bk) * N_PIX + col0 + bn];
        __syncthreads();
#pragma unroll
        for (int k = 0; k < 16; k++) {
            float4 a = *(float4*)&As[k][ty * 4];
            float4 bb = *(float4*)&Bs[k][tx * 4];
            acc[0][0] += a.x * bb.x; acc[0][1] += a.x * bb.y; acc[0][2] += a.x * bb.z; acc[0][3] += a.x * bb.w;
            acc[1][0] += a.y * bb.x; acc[1][1] += a.y * bb.y; acc[1][2] += a.y * bb.z; acc[1][3] += a.y * bb.w;
            acc[2][0] += a.z * bb.x; acc[2][1] += a.z * bb.y; acc[2][2] += a.z * bb.z; acc[2][3] += a.z * bb.w;
            acc[3][0] += a.w * bb.x; acc[3][1] += a.w * bb.y; acc[3][2] += a.w * bb.z; acc[3][3] += a.w * bb.w;
        }
        __syncthreads();
    }
    // epilogue: scale by per-pixel norm, route to q/k/v [b][h][p][f]
    int obase = row0 + ty * 4;             // 4 consecutive o → same t,h; f = fb..fb+3
    int t  = obase >> 7;
    int h  = (obase >> 5) & 3;
    int fb = obase & 31;
    float* dst = (t == 0) ? g_q : (t == 1) ? g_k : g_v;
#pragma unroll
    for (int j = 0; j < 4; j++) {
        int p = col0 + tx * 4 + j;
        float s = g_scl[b * N_PIX + p];
        float4 r = make_float4(acc[0][j] * s, acc[1][j] * s, acc[2][j] * s, acc[3][j] * s);
        *(float4*)&dst[(((size_t)b * NH + h) * N_PIX + p) * DH + fb] = r;
    }
}

// ---------------- kernel 3: flash attention (1 row/thread, 128 rows/block) ----------------
__global__ void flash_kernel() {
    __shared__ float Ks[64 * DH];
    __shared__ float Vs[64 * DH];
    int bh = blockIdx.y;                          // 0..7  (b*4+h)
    int r  = blockIdx.x * 128 + threadIdx.x;      // query row
    const float* qp = g_q + ((size_t)bh * N_PIX + r) * DH;
    const float* kb = g_k + (size_t)bh * N_PIX * DH;
    const float* vb = g_v + (size_t)bh * N_PIX * DH;

    float4 q[8], o[8];
#pragma unroll
    for (int i = 0; i < 8; i++) {
        q[i] = *(const float4*)&qp[i * 4];
        o[i] = make_float4(0.f, 0.f, 0.f, 0.f);
    }
    float m = -1e30f, l = 0.f;

    for (int t0 = 0; t0 < N_PIX; t0 += 64) {
        __syncthreads();
        const float4* ksrc = (const float4*)(kb + (size_t)t0 * DH);
        const float4* vsrc = (const float4*)(vb + (size_t)t0 * DH);
#pragma unroll
        for (int i = 0; i < 4; i++) {
            ((float4*)Ks)[threadIdx.x + i * 128] = ksrc[threadIdx.x + i * 128];
            ((float4*)Vs)[threadIdx.x + i * 128] = vsrc[threadIdx.x + i * 128];
        }
        __syncthreads();
#pragma unroll 2
        for (int j = 0; j < 64; j++) {
            const float4* kr = (const float4*)&Ks[j * DH];
            float s = 0.f;
#pragma unroll
            for (int i = 0; i < 8; i++) {
                float4 kv = kr[i];
                s += q[i].x * kv.x + q[i].y * kv.y + q[i].z * kv.z + q[i].w * kv.w;
            }
            s *= ATT_SCALE;
            if (s > m) {
                float corr = __expf(m - s);
                l *= corr;
#pragma unroll
                for (int i = 0; i < 8; i++) {
                    o[i].x *= corr; o[i].y *= corr; o[i].z *= corr; o[i].w *= corr;
                }
                m = s;
            }
            float p = __expf(s - m);
            l += p;
            const float4* vr = (const float4*)&Vs[j * DH];
#pragma unroll
            for (int i = 0; i < 8; i++) {
                float4 vv = vr[i];
                o[i].x += p * vv.x; o[i].y += p * vv.y;
                o[i].z += p * vv.z; o[i].w += p * vv.w;
            }
        }
    }
    float inv = ATT_SCALE / l;                    // second SCALE application folded here
    int b = bh >> 2, h = bh & 3;
    float* ao = g_ao + ((size_t)b * HID + h * DH) * N_PIX + r;
#pragma unroll
    for (int i = 0; i < 8; i++) {
        ao[(size_t)(i * 4 + 0) * N_PIX] = o[i].x * inv;
        ao[(size_t)(i * 4 + 1) * N_PIX] = o[i].y * inv;
        ao[(size_t)(i * 4 + 2) * N_PIX] = o[i].z * inv;
        ao[(size_t)(i * 4 + 3) * N_PIX] = o[i].w * inv;
    }
}

// ---------------- kernel 4: output projection GEMM + bias ----------------
__global__ void out_gemm(const float* __restrict__ w,
                         const float* __restrict__ bias,
                         float* __restrict__ out) {
    __shared__ float As[16][64];
    __shared__ float Bs[16][64];
    int b    = blockIdx.z;
    int row0 = blockIdx.y * 64;    // o (0..255)
    int col0 = blockIdx.x * 64;    // p
    int tid  = threadIdx.x;
    int tx = tid & 15, ty = tid >> 4;

    const float* Bbase = g_ao + (size_t)b * HID * N_PIX;
    float acc[4][4];
#pragma unroll
    for (int i = 0; i < 4; i++)
#pragma unroll
        for (int j = 0; j < 4; j++) acc[i][j] = 0.f;

    int am = tid >> 2;
    int ak = (tid & 3) * 4;
    int bk = tid >> 4;
    int bn = (tid & 15) * 4;

    for (int k0 = 0; k0 < HID; k0 += 16) {
        float4 av = *(const float4*)&w[(size_t)(row0 + am) * HID + k0 + ak];
        As[ak + 0][am] = av.x;
        As[ak + 1][am] = av.y;
        As[ak + 2][am] = av.z;
        As[ak + 3][am] = av.w;
        *(float4*)&Bs[bk][bn] =
            *(const float4*)&Bbase[(size_t)(k0 + bk) * N_PIX + col0 + bn];
        __syncthreads();
#pragma unroll
        for (int k = 0; k < 16; k++) {
            float4 a = *(float4*)&As[k][ty * 4];
            float4 bb = *(float4*)&Bs[k][tx * 4];
            acc[0][0] += a.x * bb.x; acc[0][1] += a.x * bb.y; acc[0][2] += a.x * bb.z; acc[0][3] += a.x * bb.w;
            acc[1][0] += a.y * bb.x; acc[1][1] += a.y * bb.y; acc[1][2] += a.y * bb.z; acc[1][3] += a.y * bb.w;
            acc[2][0] += a.z * bb.x; acc[2][1] += a.z * bb.y; acc[2][2] += a.z * bb.z; acc[2][3] += a.z * bb.w;
            acc[3][0] += a.w * bb.x; acc[3][1] += a.w * bb.y; acc[3][2] += a.w * bb.z; acc[3][3] += a.w * bb.w;
        }
        __syncthreads();
    }
#pragma unroll
    for (int i = 0; i < 4; i++) {
        int oc = row0 + ty * 4 + i;
        float bi = bias[oc];
        float4 r = make_float4(acc[i][0] + bi, acc[i][1] + bi, acc[i][2] + bi, acc[i][3] + bi);
        *(float4*)&out[((size_t)b * CDIM + oc) * N_PIX + col0 + tx * 4] = r;
    }
}

// ---------------- launcher ----------------
extern "C" void kernel_launch(void* const* d_in, const int* in_sizes, int n_in,
                              void* d_out, int out_size) {
    const float* x     = (const float*)d_in[0];
    const float* gvec  = (const float*)d_in[1];
    const float* w_qkv = (const float*)d_in[2];
    const float* w_out = (const float*)d_in[3];
    const float* b_out = (const float*)d_in[4];
    float* out = (float*)d_out;

    norm_kernel<<<(BATCH * N_PIX) / 256, 256>>>(x);

    dim3 g1(N_PIX / 64, (3 * HID) / 64, BATCH);   // 64 x 6 x 2
    qkv_gemm<<<g1, 256>>>(x, gvec, w_qkv);

    dim3 g2(N_PIX / 128, BATCH * NH);             // 32 x 8
    flash_kernel<<<g2, 128>>>();

    dim3 g3(N_PIX / 64, CDIM / 64, BATCH);        // 64 x 4 x 2
    out_gemm<<<g3, 256>>>(w_out, b_out, out);
}

// round 3
// speedup vs baseline: 3.1809x; 3.1809x over previous
#include <cuda_runtime.h>
#include <math.h>
#include <stdint.h>

#define N_PIX 4096
#define CDIM  256
#define HID   128
#define NH    4
#define DH    32
#define BATCH 2
#define ATT_SCALE 0.17677669529663687f   // 32^-0.5

// ---------------- scratch (static device globals; no allocs) ----------------
__device__ float g_q [BATCH * NH * N_PIX * DH];   // [b][h][n][f]
__device__ float g_k [BATCH * NH * N_PIX * DH];   // [b][h][n][f]
__device__ float g_v [BATCH * NH * N_PIX * DH];   // [b][h][n][f]
__device__ float g_ao[BATCH * HID * N_PIX];       // [b][h*32+f][n]
__device__ float g_scl[BATCH * N_PIX];            // per-pixel 16/max(||x||,eps)

__device__ __forceinline__ uint32_t f2tf(float f) {
    uint32_t r;
    asm("cvt.rna.tf32.f32 %0, %1;" : "=r"(r) : "f"(f));
    return r;
}
#define MMA_TF32(c, a, b0_, b1_) \
    asm volatile("mma.sync.aligned.m16n8k8.row.col.f32.tf32.tf32.f32 " \
        "{%0,%1,%2,%3},{%4,%5,%6,%7},{%8,%9},{%0,%1,%2,%3};" \
        : "+f"((c)[0]), "+f"((c)[1]), "+f"((c)[2]), "+f"((c)[3]) \
        : "r"((a)[0]), "r"((a)[1]), "r"((a)[2]), "r"((a)[3]), "r"(b0_), "r"(b1_))

// ---------------- kernel 1: per-pixel channel-norm scale ----------------
__global__ void norm_kernel(const float* __restrict__ x) {
    int p   = blockIdx.x * 256 + threadIdx.x;
    int b   = p >> 12;
    int pix = p & (N_PIX - 1);
    const float* xb = x + (size_t)b * CDIM * N_PIX + pix;
    float ss = 0.f;
#pragma unroll 8
    for (int c = 0; c < CDIM; c++) {
        float v = xb[(size_t)c * N_PIX];
        ss += v * v;
    }
    g_scl[p] = 16.0f / fmaxf(sqrtf(ss), 1e-12f);
}

// ---------------- kernel 2: QKV GEMM ----------------
__global__ void qkv_gemm(const float* __restrict__ x,
                         const float* __restrict__ gvec,
                         const float* __restrict__ w) {
    __shared__ float As[16][64];
    __shared__ float Bs[16][64];
    int b    = blockIdx.z;
    int row0 = blockIdx.y * 64;
    int col0 = blockIdx.x * 64;
    int tid  = threadIdx.x;
    int tx = tid & 15, ty = tid >> 4;

    const float* Bbase = x + (size_t)b * CDIM * N_PIX;
    float acc[4][4];
#pragma unroll
    for (int i = 0; i < 4; i++)
#pragma unroll
        for (int j = 0; j < 4; j++) acc[i][j] = 0.f;

    int am = tid >> 2, ak = (tid & 3) * 4;
    int bk = tid >> 4, bn = (tid & 15) * 4;

    for (int k0 = 0; k0 < CDIM; k0 += 16) {
        float4 av = *(const float4*)&w[(size_t)(row0 + am) * CDIM + k0 + ak];
        float4 gv = *(const float4*)&gvec[k0 + ak];
        As[ak + 0][am] = av.x * gv.x;
        As[ak + 1][am] = av.y * gv.y;
        As[ak + 2][am] = av.z * gv.z;
        As[ak + 3][am] = av.w * gv.w;
        *(float4*)&Bs[bk][bn] =
            *(const float4*)&Bbase[(size_t)(k0 + bk) * N_PIX + col0 + bn];
        __syncthreads();
#pragma unroll
        for (int k = 0; k < 16; k++) {
            float4 a = *(float4*)&As[k][ty * 4];
            float4 bb = *(float4*)&Bs[k][tx * 4];
            acc[0][0] += a.x * bb.x; acc[0][1] += a.x * bb.y; acc[0][2] += a.x * bb.z; acc[0][3] += a.x * bb.w;
            acc[1][0] += a.y * bb.x; acc[1][1] += a.y * bb.y; acc[1][2] += a.y * bb.z; acc[1][3] += a.y * bb.w;
            acc[2][0] += a.z * bb.x; acc[2][1] += a.z * bb.y; acc[2][2] += a.z * bb.z; acc[2][3] += a.z * bb.w;
            acc[3][0] += a.w * bb.x; acc[3][1] += a.w * bb.y; acc[3][2] += a.w * bb.z; acc[3][3] += a.w * bb.w;
        }
        __syncthreads();
    }
    int obase = row0 + ty * 4;
    int t  = obase >> 7;
    int h  = (obase >> 5) & 3;
    int fb = obase & 31;
    float* dst = (t == 0) ? g_q : (t == 1) ? g_k : g_v;
#pragma unroll
    for (int j = 0; j < 4; j++) {
        int p = col0 + tx * 4 + j;
        float s = g_scl[b * N_PIX + p];
        float4 r = make_float4(acc[0][j] * s, acc[1][j] * s, acc[2][j] * s, acc[3][j] * s);
        *(float4*)&dst[(((size_t)b * NH + h) * N_PIX + p) * DH + fb] = r;
    }
}

// ---------------- kernel 3: tf32 mma.sync flash attention ----------------
// Logits bounded (|s| < ~10), so exp without max-subtraction is safe; O
// accumulates in registers across all KV tiles (no rescale pass).
#define KV_PAD 40     // row pitch (floats) for K/V tiles: conflict-free frag reads
#define P_PAD  132    // row pitch for per-warp P tile: conflict-free A-frag reads
#define SMEM_FLOATS (2 * 128 * KV_PAD + 4 * 32 * P_PAD)   // 27136
#define SMEM_BYTES  (SMEM_FLOATS * 4)                     // 108544

__global__ void __launch_bounds__(128) flash_mma() {
    extern __shared__ uint32_t sm[];
    uint32_t* Ku = sm;                       // [128][KV_PAD] tf32 bits
    uint32_t* Vu = sm + 128 * KV_PAD;        // [128][KV_PAD]
    int tid = threadIdx.x;
    int w   = tid >> 5, lane = tid & 31;
    int g   = lane >> 2, tig = lane & 3;
    uint32_t* Pu = sm + 2 * 128 * KV_PAD + w * 32 * P_PAD;  // warp-private [32][P_PAD]

    int bh = blockIdx.y;
    int r0 = blockIdx.x * 128;
    int qb = r0 + w * 32;

    // Q fragments (scale folded, tf32)
    const float* qp = g_q + ((size_t)bh * N_PIX + qb) * DH;
    uint32_t qa[2][4][4];
#pragma unroll
    for (int mi = 0; mi < 2; mi++)
#pragma unroll
        for (int kt = 0; kt < 4; kt++) {
            int rl = mi * 16 + g, rh = rl + 8;
            int cl = kt * 8 + tig, ch = cl + 4;
            qa[mi][kt][0] = f2tf(qp[rl * DH + cl] * ATT_SCALE);
            qa[mi][kt][1] = f2tf(qp[rh * DH + cl] * ATT_SCALE);
            qa[mi][kt][2] = f2tf(qp[rl * DH + ch] * ATT_SCALE);
            qa[mi][kt][3] = f2tf(qp[rh * DH + ch] * ATT_SCALE);
        }

    const float4* kbase = (const float4*)(g_k + (size_t)bh * N_PIX * DH);
    const float4* vbase = (const float4*)(g_v + (size_t)bh * N_PIX * DH);

    float oacc[2][4][4];
#pragma unroll
    for (int mi = 0; mi < 2; mi++)
#pragma unroll
        for (int nf = 0; nf < 4; nf++)
#pragma unroll
            for (int i = 0; i < 4; i++) oacc[mi][nf][i] = 0.f;
    float lsum[2][2] = {{0.f, 0.f}, {0.f, 0.f}};

    for (int t = 0; t < 32; t++) {
        __syncthreads();   // prev tile's K/V reads and P reuse complete
        // stage K/V tile [128 kv][32 f] -> smem (tf32-converted)
#pragma unroll
        for (int i = tid; i < 1024; i += 128) {
            int kv = i >> 3, f4 = (i & 7) * 4;
            float4 kvv = kbase[t * 1024 + i];
            uint32_t* kd = Ku + kv * KV_PAD + f4;
            kd[0] = f2tf(kvv.x); kd[1] = f2tf(kvv.y);
            kd[2] = f2tf(kvv.z); kd[3] = f2tf(kvv.w);
            float4 vvv = vbase[t * 1024 + i];
            uint32_t* vd = Vu + kv * KV_PAD + f4;
            vd[0] = f2tf(vvv.x); vd[1] = f2tf(vvv.y);
            vd[2] = f2tf(vvv.z); vd[3] = f2tf(vvv.w);
        }
        __syncthreads();

        // S = Q K^T in 32-col chunks; P = exp(S) -> warp-private smem
#pragma unroll
        for (int chk = 0; chk < 4; chk++) {
            float sacc[2][4][4];
#pragma unroll
            for (int mi = 0; mi < 2; mi++)
#pragma unroll
                for (int ni = 0; ni < 4; ni++)
#pragma unroll
                    for (int i = 0; i < 4; i++) sacc[mi][ni][i] = 0.f;
#pragma unroll
            for (int kt = 0; kt < 4; kt++)
#pragma unroll
                for (int ni = 0; ni < 4; ni++) {
                    int n = chk * 32 + ni * 8 + g;
                    uint32_t b0 = Ku[n * KV_PAD + kt * 8 + tig];
                    uint32_t b1 = Ku[n * KV_PAD + kt * 8 + tig + 4];
                    MMA_TF32(sacc[0][ni], qa[0][kt], b0, b1);
                    MMA_TF32(sacc[1][ni], qa[1][kt], b0, b1);
                }
#pragma unroll
            for (int mi = 0; mi < 2; mi++)
#pragma unroll
                for (int ni = 0; ni < 4; ni++) {
                    float p0 = __expf(sacc[mi][ni][0]);
                    float p1 = __expf(sacc[mi][ni][1]);
                    float p2 = __expf(sacc[mi][ni][2]);
                    float p3 = __expf(sacc[mi][ni][3]);
                    lsum[mi][0] += p0 + p1;
                    lsum[mi][1] += p2 + p3;
                    int col = chk * 32 + ni * 8 + 2 * tig;
                    uint32_t* pr = Pu + (mi * 16 + g) * P_PAD + col;
                    pr[0] = f2tf(p0); pr[1] = f2tf(p1);
                    pr += 8 * P_PAD;
                    pr[0] = f2tf(p2); pr[1] = f2tf(p3);
                }
        }
        __syncwarp();   // P visible across lanes of this warp

        // O += P V   (K = 128)
#pragma unroll
        for (int kt = 0; kt < 16; kt++) {
            uint32_t pa[2][4];
#pragma unroll
            for (int mi = 0; mi < 2; mi++) {
                const uint32_t* pb = Pu + (mi * 16 + g) * P_PAD + kt * 8 + tig;
                pa[mi][0] = pb[0];
                pa[mi][1] = pb[8 * P_PAD];
                pa[mi][2] = pb[4];
                pa[mi][3] = pb[8 * P_PAD + 4];
            }
#pragma unroll
            for (int nf = 0; nf < 4; nf++) {
                uint32_t vb0 = Vu[(kt * 8 + tig) * KV_PAD + nf * 8 + g];
                uint32_t vb1 = Vu[(kt * 8 + tig + 4) * KV_PAD + nf * 8 + g];
                MMA_TF32(oacc[0][nf], pa[0], vb0, vb1);
                MMA_TF32(oacc[1][nf], pa[1], vb0, vb1);
            }
        }
    }

    // reduce lsum across the 4-thread column group (lanes differ in bits 0-1)
    float inv[2][2];
#pragma unroll
    for (int mi = 0; mi < 2; mi++)
#pragma unroll
        for (int hf = 0; hf < 2; hf++) {
            float v = lsum[mi][hf];
            v += __shfl_xor_sync(0xFFFFFFFF, v, 1);
            v += __shfl_xor_sync(0xFFFFFFFF, v, 2);
            inv[mi][hf] = ATT_SCALE / v;     // second SCALE folded here
        }

    int b = bh >> 2, h = bh & 3;
    float* ao = g_ao + (size_t)(b * HID + h * DH) * N_PIX;
#pragma unroll
    for (int mi = 0; mi < 2; mi++)
#pragma unroll
        for (int nf = 0; nf < 4; nf++) {
            int f = nf * 8 + 2 * tig;
            int rlo = qb + mi * 16 + g, rhi = rlo + 8;
            ao[(size_t)f * N_PIX + rlo]       = oacc[mi][nf][0] * inv[mi][0];
            ao[(size_t)(f + 1) * N_PIX + rlo] = oacc[mi][nf][1] * inv[mi][0];
            ao[(size_t)f * N_PIX + rhi]       = oacc[mi][nf][2] * inv[mi][1];
            ao[(size_t)(f + 1) * N_PIX + rhi] = oacc[mi][nf][3] * inv[mi][1];
        }
}

// ---------------- kernel 4: output projection GEMM + bias ----------------
__global__ void out_gemm(const float* __restrict__ w,
                         const float* __restrict__ bias,
                         float* __restrict__ out) {
    __shared__ float As[16][64];
    __shared__ float Bs[16][64];
    int b    = blockIdx.z;
    int row0 = blockIdx.y * 64;
    int col0 = blockIdx.x * 64;
    int tid  = threadIdx.x;
    int tx = tid & 15, ty = tid >> 4;

    const float* Bbase = g_ao + (size_t)b * HID * N_PIX;
    float acc[4][4];
#pragma unroll
    for (int i = 0; i < 4; i++)
#pragma unroll
        for (int j = 0; j < 4; j++) acc[i][j] = 0.f;

    int am = tid >> 2, ak = (tid & 3) * 4;
    int bk = tid >> 4, bn = (tid & 15) * 4;

    for (int k0 = 0; k0 < HID; k0 += 16) {
        float4 av = *(const float4*)&w[(size_t)(row0 + am) * HID + k0 + ak];
        As[ak + 0][am] = av.x;
        As[ak + 1][am] = av.y;
        As[ak + 2][am] = av.z;
        As[ak + 3][am] = av.w;
        *(float4*)&Bs[bk][bn] =
            *(const float4*)&Bbase[(size_t)(k0 + bk) * N_PIX + col0 + bn];
        __syncthreads();
#pragma unroll
        for (int k = 0; k < 16; k++) {
            float4 a = *(float4*)&As[k][ty * 4];
            float4 bb = *(float4*)&Bs[k][tx * 4];
            acc[0][0] += a.x * bb.x; acc[0][1] += a.x * bb.y; acc[0][2] += a.x * bb.z; acc[0][3] += a.x * bb.w;
            acc[1][0] += a.y * bb.x; acc[1][1] += a.y * bb.y; acc[1][2] += a.y * bb.z; acc[1][3] += a.y * bb.w;
            acc[2][0] += a.z * bb.x; acc[2][1] += a.z * bb.y; acc[2][2] += a.z * bb.z; acc[2][3] += a.z * bb.w;
            acc[3][0] += a.w * bb.x; acc[3][1] += a.w * bb.y; acc[3][2] += a.w * bb.z; acc[3][3] += a.w * bb.w;
        }
        __syncthreads();
    }
#pragma unroll
    for (int i = 0; i < 4; i++) {
        int oc = row0 + ty * 4 + i;
        float bi = bias[oc];
        float4 r = make_float4(acc[i][0] + bi, acc[i][1] + bi, acc[i][2] + bi, acc[i][3] + bi);
        *(float4*)&out[((size_t)b * CDIM + oc) * N_PIX + col0 + tx * 4] = r;
    }
}

// ---------------- launcher ----------------
extern "C" void kernel_launch(void* const* d_in, const int* in_sizes, int n_in,
                              void* d_out, int out_size) {
    const float* x     = (const float*)d_in[0];
    const float* gvec  = (const float*)d_in[1];
    const float* w_qkv = (const float*)d_in[2];
    const float* w_out = (const float*)d_in[3];
    const float* b_out = (const float*)d_in[4];
    float* out = (float*)d_out;

    static int smem_set = 0;
    if (!smem_set) {
        cudaFuncSetAttribute(flash_mma, cudaFuncAttributeMaxDynamicSharedMemorySize,
                             SMEM_BYTES);
        smem_set = 1;
    }

    norm_kernel<<<(BATCH * N_PIX) / 256, 256>>>(x);

    dim3 g1(N_PIX / 64, (3 * HID) / 64, BATCH);
    qkv_gemm<<<g1, 256>>>(x, gvec, w_qkv);

    dim3 g2(N_PIX / 128, BATCH * NH);
    flash_mma<<<g2, 128, SMEM_BYTES>>>();

    dim3 g3(N_PIX / 64, CDIM / 64, BATCH);
    out_gemm<<<g3, 256>>>(w_out, b_out, out);
}

// round 4
// speedup vs baseline: 4.1622x; 1.3085x over previous
#include <cuda_runtime.h>
#include <math.h>
#include <stdint.h>

#define N_PIX 4096
#define CDIM  256
#define HID   128
#define NH    4
#define DH    32
#define BATCH 2
#define ATT_SCALE 0.17677669529663687f   // 32^-0.5

// ---------------- scratch (static device globals; no allocs) ----------------
__device__ float g_q [BATCH * NH * N_PIX * DH];   // [b][h][n][f]
__device__ float g_k [BATCH * NH * N_PIX * DH];   // [b][h][n][f]
__device__ float g_v [BATCH * NH * N_PIX * DH];   // [b][h][n][f]
__device__ float g_ao[BATCH * HID * N_PIX];       // [b][h*32+f][n]
__device__ float g_scl[BATCH * N_PIX];            // per-pixel 16/max(||x||,eps)

__device__ __forceinline__ uint32_t f2tf(float f) {
    uint32_t r;
    asm("cvt.rna.tf32.f32 %0, %1;" : "=r"(r) : "f"(f));
    return r;
}
#define MMA_TF32(c, a, b0_, b1_) \
    asm volatile("mma.sync.aligned.m16n8k8.row.col.f32.tf32.tf32.f32 " \
        "{%0,%1,%2,%3},{%4,%5,%6,%7},{%8,%9},{%0,%1,%2,%3};" \
        : "+f"((c)[0]), "+f"((c)[1]), "+f"((c)[2]), "+f"((c)[3]) \
        : "r"((a)[0]), "r"((a)[1]), "r"((a)[2]), "r"((a)[3]), "r"(b0_), "r"(b1_))

// ---------------- kernel 1: per-pixel channel-norm scale ----------------
__global__ void norm_kernel(const float* __restrict__ x) {
    int p   = blockIdx.x * 256 + threadIdx.x;
    int b   = p >> 12;
    int pix = p & (N_PIX - 1);
    const float* xb = x + (size_t)b * CDIM * N_PIX + pix;
    float ss = 0.f;
#pragma unroll 8
    for (int c = 0; c < CDIM; c++) {
        float v = xb[(size_t)c * N_PIX];
        ss += v * v;
    }
    g_scl[p] = 16.0f / fmaxf(sqrtf(ss), 1e-12f);
}

// ---------------- kernel 2: QKV GEMM via tf32 mma ----------------
// C[o][p] = scl[p] * sum_c (w[o][c]*g[c]) * x[b][c][p]; CTA tile 128x128, K-tile 16.
#define PA 20    // As [128 m][PA k]
#define PB 136   // Bs [16 k][PB n]
__global__ void __launch_bounds__(256) qkv_mma(const float* __restrict__ x,
                                               const float* __restrict__ gvec,
                                               const float* __restrict__ w) {
    __shared__ uint32_t As[128 * PA];
    __shared__ uint32_t Bs[16 * PB];
    int b = blockIdx.z, row0 = blockIdx.y * 128, col0 = blockIdx.x * 128;
    int tid = threadIdx.x, wid = tid >> 5, lane = tid & 31;
    int wm = wid >> 2, wn = wid & 3;
    int g = lane >> 2, tig = lane & 3;
    const float* Bbase = x + (size_t)b * CDIM * N_PIX;

    float acc[4][4][4];
#pragma unroll
    for (int mi = 0; mi < 4; mi++)
#pragma unroll
        for (int ni = 0; ni < 4; ni++)
#pragma unroll
            for (int i = 0; i < 4; i++) acc[mi][ni][i] = 0.f;

    for (int k0 = 0; k0 < CDIM; k0 += 16) {
#pragma unroll
        for (int i = tid; i < 512; i += 256) {          // A: 128m x 16k
            int m = i >> 2, k4 = (i & 3) * 4;
            float4 wv = *(const float4*)&w[(size_t)(row0 + m) * CDIM + k0 + k4];
            float4 gv = *(const float4*)&gvec[k0 + k4];
            uint4 o;
            o.x = f2tf(wv.x * gv.x); o.y = f2tf(wv.y * gv.y);
            o.z = f2tf(wv.z * gv.z); o.w = f2tf(wv.w * gv.w);
            *(uint4*)&As[m * PA + k4] = o;
        }
#pragma unroll
        for (int i = tid; i < 512; i += 256) {          // B: 16k x 128n
            int k = i >> 5, p4 = (i & 31) * 4;
            float4 xv = *(const float4*)&Bbase[(size_t)(k0 + k) * N_PIX + col0 + p4];
            uint4 o;
            o.x = f2tf(xv.x); o.y = f2tf(xv.y); o.z = f2tf(xv.z); o.w = f2tf(xv.w);
            *(uint4*)&Bs[k * PB + p4] = o;
        }
        __syncthreads();
#pragma unroll
        for (int ks = 0; ks < 2; ks++) {
            uint32_t af[4][4];
#pragma unroll
            for (int mi = 0; mi < 4; mi++) {
                int r = (wm * 64 + mi * 16 + g) * PA + ks * 8 + tig;
                af[mi][0] = As[r];
                af[mi][1] = As[r + 8 * PA];
                af[mi][2] = As[r + 4];
                af[mi][3] = As[r + 8 * PA + 4];
            }
#pragma unroll
            for (int ni = 0; ni < 4; ni++) {
                int nb = (ks * 8 + tig) * PB + wn * 32 + ni * 8 + g;
                uint32_t b0 = Bs[nb];
                uint32_t b1 = Bs[nb + 4 * PB];
#pragma unroll
                for (int mi = 0; mi < 4; mi++)
                    MMA_TF32(acc[mi][ni], af[mi], b0, b1);
            }
        }
        __syncthreads();
    }
    // epilogue: scale by scl[p], route to q/k/v
    int t = row0 >> 7;
    float* dst = (t == 0) ? g_q : (t == 1) ? g_k : g_v;
    const float* scl = g_scl + b * N_PIX;
#pragma unroll
    for (int mi = 0; mi < 4; mi++) {
        int o_lo = row0 + wm * 64 + mi * 16 + g;
        int h = (o_lo >> 5) & 3;
        int f = o_lo & 31;
        float* d0 = dst + ((size_t)(b * NH + h) * N_PIX) * DH;
#pragma unroll
        for (int ni = 0; ni < 4; ni++) {
            int p = col0 + wn * 32 + ni * 8 + 2 * tig;
            float s0 = scl[p], s1 = scl[p + 1];
            d0[(size_t)p * DH + f]           = acc[mi][ni][0] * s0;
            d0[(size_t)(p + 1) * DH + f]     = acc[mi][ni][1] * s1;
            d0[(size_t)p * DH + f + 8]       = acc[mi][ni][2] * s0;
            d0[(size_t)(p + 1) * DH + f + 8] = acc[mi][ni][3] * s1;
        }
    }
}

// ---------------- kernel 3: tf32 mma.sync flash attention (chunk-fused) ----------------
#define K_PAD 36
#define V_PAD 40
#define P_PAD 36
#define SMEM_FLASH ((128 * K_PAD + 128 * V_PAD + 4 * 32 * P_PAD) * 4)   // 57344

__global__ void __launch_bounds__(128) flash_mma() {
    extern __shared__ uint32_t sm[];
    uint32_t* Ku = sm;                               // [128][K_PAD]
    uint32_t* Vu = sm + 128 * K_PAD;                 // [128][V_PAD]
    int tid = threadIdx.x;
    int w   = tid >> 5, lane = tid & 31;
    int g   = lane >> 2, tig = lane & 3;
    uint32_t* Pu = sm + 128 * K_PAD + 128 * V_PAD + w * 32 * P_PAD;  // [32][P_PAD]

    int bh = blockIdx.y;
    int r0 = blockIdx.x * 128;
    int qb = r0 + w * 32;

    const float* qp = g_q + ((size_t)bh * N_PIX + qb) * DH;
    uint32_t qa[2][4][4];
#pragma unroll
    for (int mi = 0; mi < 2; mi++)
#pragma unroll
        for (int kt = 0; kt < 4; kt++) {
            int rl = mi * 16 + g, rh = rl + 8;
            int cl = kt * 8 + tig, ch = cl + 4;
            qa[mi][kt][0] = f2tf(qp[rl * DH + cl] * ATT_SCALE);
            qa[mi][kt][1] = f2tf(qp[rh * DH + cl] * ATT_SCALE);
            qa[mi][kt][2] = f2tf(qp[rl * DH + ch] * ATT_SCALE);
            qa[mi][kt][3] = f2tf(qp[rh * DH + ch] * ATT_SCALE);
        }

    const float4* kbase = (const float4*)(g_k + (size_t)bh * N_PIX * DH);
    const float4* vbase = (const float4*)(g_v + (size_t)bh * N_PIX * DH);

    float oacc[2][4][4];
#pragma unroll
    for (int mi = 0; mi < 2; mi++)
#pragma unroll
        for (int nf = 0; nf < 4; nf++)
#pragma unroll
            for (int i = 0; i < 4; i++) oacc[mi][nf][i] = 0.f;
    float lsum[2][2] = {{0.f, 0.f}, {0.f, 0.f}};

    for (int t = 0; t < 32; t++) {
        __syncthreads();
#pragma unroll
        for (int i = tid; i < 1024; i += 128) {
            int kv = i >> 3, f4 = (i & 7) * 4;
            float4 kvv = kbase[t * 1024 + i];
            uint4 kk;
            kk.x = f2tf(kvv.x); kk.y = f2tf(kvv.y);
            kk.z = f2tf(kvv.z); kk.w = f2tf(kvv.w);
            *(uint4*)&Ku[kv * K_PAD + f4] = kk;
            float4 vvv = vbase[t * 1024 + i];
            uint4 vv;
            vv.x = f2tf(vvv.x); vv.y = f2tf(vvv.y);
            vv.z = f2tf(vvv.z); vv.w = f2tf(vvv.w);
            *(uint4*)&Vu[kv * V_PAD + f4] = vv;
        }
        __syncthreads();

#pragma unroll
        for (int chk = 0; chk < 4; chk++) {
            // S chunk: 32 rows (per warp) x 32 cols
            float sacc[2][4][4];
#pragma unroll
            for (int mi = 0; mi < 2; mi++)
#pragma unroll
                for (int ni = 0; ni < 4; ni++)
#pragma unroll
                    for (int i = 0; i < 4; i++) sacc[mi][ni][i] = 0.f;
#pragma unroll
            for (int kt = 0; kt < 4; kt++)
#pragma unroll
                for (int ni = 0; ni < 4; ni++) {
                    int n = chk * 32 + ni * 8 + g;
                    uint32_t b0 = Ku[n * K_PAD + kt * 8 + tig];
                    uint32_t b1 = Ku[n * K_PAD + kt * 8 + tig + 4];
                    MMA_TF32(sacc[0][ni], qa[0][kt], b0, b1);
                    MMA_TF32(sacc[1][ni], qa[1][kt], b0, b1);
                }
            // exp + lsum + P chunk to warp-private smem
#pragma unroll
            for (int mi = 0; mi < 2; mi++)
#pragma unroll
                for (int ni = 0; ni < 4; ni++) {
                    float p0 = __expf(sacc[mi][ni][0]);
                    float p1 = __expf(sacc[mi][ni][1]);
                    float p2 = __expf(sacc[mi][ni][2]);
                    float p3 = __expf(sacc[mi][ni][3]);
                    lsum[mi][0] += p0 + p1;
                    lsum[mi][1] += p2 + p3;
                    uint32_t* pr = Pu + (mi * 16 + g) * P_PAD + ni * 8 + 2 * tig;
                    pr[0] = f2tf(p0); pr[1] = f2tf(p1);
                    pr[8 * P_PAD] = f2tf(p2); pr[8 * P_PAD + 1] = f2tf(p3);
                }
            __syncwarp();
            // O += P_chunk * V_chunk  (K = 32)
#pragma unroll
            for (int kt = 0; kt < 4; kt++) {
                uint32_t pa[2][4];
#pragma unroll
                for (int mi = 0; mi < 2; mi++) {
                    const uint32_t* pb = Pu + (mi * 16 + g) * P_PAD + kt * 8 + tig;
                    pa[mi][0] = pb[0];
                    pa[mi][1] = pb[8 * P_PAD];
                    pa[mi][2] = pb[4];
                    pa[mi][3] = pb[8 * P_PAD + 4];
                }
                int vrow = chk * 32 + kt * 8 + tig;
#pragma unroll
                for (int nf = 0; nf < 4; nf++) {
                    uint32_t vb0 = Vu[vrow * V_PAD + nf * 8 + g];
                    uint32_t vb1 = Vu[(vrow + 4) * V_PAD + nf * 8 + g];
                    MMA_TF32(oacc[0][nf], pa[0], vb0, vb1);
                    MMA_TF32(oacc[1][nf], pa[1], vb0, vb1);
                }
            }
            __syncwarp();   // P reuse next chunk
        }
    }

    float inv[2][2];
#pragma unroll
    for (int mi = 0; mi < 2; mi++)
#pragma unroll
        for (int hf = 0; hf < 2; hf++) {
            float v = lsum[mi][hf];
            v += __shfl_xor_sync(0xFFFFFFFF, v, 1);
            v += __shfl_xor_sync(0xFFFFFFFF, v, 2);
            inv[mi][hf] = ATT_SCALE / v;
        }

    int b = bh >> 2, h = bh & 3;
    float* ao = g_ao + (size_t)(b * HID + h * DH) * N_PIX;
#pragma unroll
    for (int mi = 0; mi < 2; mi++)
#pragma unroll
        for (int nf = 0; nf < 4; nf++) {
            int f = nf * 8 + 2 * tig;
            int rlo = qb + mi * 16 + g, rhi = rlo + 8;
            ao[(size_t)f * N_PIX + rlo]       = oacc[mi][nf][0] * inv[mi][0];
            ao[(size_t)(f + 1) * N_PIX + rlo] = oacc[mi][nf][1] * inv[mi][0];
            ao[(size_t)f * N_PIX + rhi]       = oacc[mi][nf][2] * inv[mi][1];
            ao[(size_t)(f + 1) * N_PIX + rhi] = oacc[mi][nf][3] * inv[mi][1];
        }
}

// ---------------- kernel 4: output projection via tf32 mma + bias ----------------
__global__ void __launch_bounds__(256) out_mma(const float* __restrict__ w,
                                               const float* __restrict__ bias,
                                               float* __restrict__ out) {
    __shared__ uint32_t As[128 * PA];
    __shared__ uint32_t Bs[16 * PB];
    int b = blockIdx.z, row0 = blockIdx.y * 128, col0 = blockIdx.x * 128;
    int tid = threadIdx.x, wid = tid >> 5, lane = tid & 31;
    int wm = wid >> 2, wn = wid & 3;
    int g = lane >> 2, tig = lane & 3;
    const float* Bbase = g_ao + (size_t)b * HID * N_PIX;

    float acc[4][4][4];
#pragma unroll
    for (int mi = 0; mi < 4; mi++)
#pragma unroll
        for (int ni = 0; ni < 4; ni++)
#pragma unroll
            for (int i = 0; i < 4; i++) acc[mi][ni][i] = 0.f;

    for (int k0 = 0; k0 < HID; k0 += 16) {
#pragma unroll
        for (int i = tid; i < 512; i += 256) {
            int m = i >> 2, k4 = (i & 3) * 4;
            float4 wv = *(const float4*)&w[(size_t)(row0 + m) * HID + k0 + k4];
            uint4 o;
            o.x = f2tf(wv.x); o.y = f2tf(wv.y); o.z = f2tf(wv.z); o.w = f2tf(wv.w);
            *(uint4*)&As[m * PA + k4] = o;
        }
#pragma unroll
        for (int i = tid; i < 512; i += 256) {
            int k = i >> 5, p4 = (i & 31) * 4;
            float4 xv = *(const float4*)&Bbase[(size_t)(k0 + k) * N_PIX + col0 + p4];
            uint4 o;
            o.x = f2tf(xv.x); o.y = f2tf(xv.y); o.z = f2tf(xv.z); o.w = f2tf(xv.w);
            *(uint4*)&Bs[k * PB + p4] = o;
        }
        __syncthreads();
#pragma unroll
        for (int ks = 0; ks < 2; ks++) {
            uint32_t af[4][4];
#pragma unroll
            for (int mi = 0; mi < 4; mi++) {
                int r = (wm * 64 + mi * 16 + g) * PA + ks * 8 + tig;
                af[mi][0] = As[r];
                af[mi][1] = As[r + 8 * PA];
                af[mi][2] = As[r + 4];
                af[mi][3] = As[r + 8 * PA + 4];
            }
#pragma unroll
            for (int ni = 0; ni < 4; ni++) {
                int nb = (ks * 8 + tig) * PB + wn * 32 + ni * 8 + g;
                uint32_t b0 = Bs[nb];
                uint32_t b1 = Bs[nb + 4 * PB];
#pragma unroll
                for (int mi = 0; mi < 4; mi++)
                    MMA_TF32(acc[mi][ni], af[mi], b0, b1);
            }
        }
        __syncthreads();
    }
#pragma unroll
    for (int mi = 0; mi < 4; mi++) {
        int o_lo = row0 + wm * 64 + mi * 16 + g;
        float b0v = bias[o_lo], b1v = bias[o_lo + 8];
        float* r0p = out + ((size_t)b * CDIM + o_lo) * N_PIX;
        float* r1p = r0p + 8 * N_PIX;
#pragma unroll
        for (int ni = 0; ni < 4; ni++) {
            int p = col0 + wn * 32 + ni * 8 + 2 * tig;
            *(float2*)&r0p[p] = make_float2(acc[mi][ni][0] + b0v, acc[mi][ni][1] + b0v);
            *(float2*)&r1p[p] = make_float2(acc[mi][ni][2] + b1v, acc[mi][ni][3] + b1v);
        }
    }
}

// ---------------- launcher ----------------
extern "C" void kernel_launch(void* const* d_in, const int* in_sizes, int n_in,
                              void* d_out, int out_size) {
    const float* x     = (const float*)d_in[0];
    const float* gvec  = (const float*)d_in[1];
    const float* w_qkv = (const float*)d_in[2];
    const float* w_out = (const float*)d_in[3];
    const float* b_out = (const float*)d_in[4];
    float* out = (float*)d_out;

    static int smem_set = 0;
    if (!smem_set) {
        cudaFuncSetAttribute(flash_mma, cudaFuncAttributeMaxDynamicSharedMemorySize,
                             SMEM_FLASH);
        smem_set = 1;
    }

    norm_kernel<<<(BATCH * N_PIX) / 256, 256>>>(x);

    dim3 g1(N_PIX / 128, 3, BATCH);               // 32 x 3 x 2
    qkv_mma<<<g1, 256>>>(x, gvec, w_qkv);

    dim3 g2(N_PIX / 128, BATCH * NH);             // 32 x 8
    flash_mma<<<g2, 128, SMEM_FLASH>>>();

    dim3 g3(N_PIX / 128, 2, BATCH);               // 32 x 2 x 2
    out_mma<<<g3, 256>>>(w_out, b_out, out);
}